// round 13
// baseline (speedup 1.0000x reference)
#include <cuda_runtime.h>
#include <cuda_bf16.h>
#include <cuda_fp16.h>
#include <math.h>
#include <stdint.h>

#define B_    512
#define D_    512
#define C_    100000
#define KNN   200
#define NCLS  1000
#define GCONST 0.005f     // 1/(2*sigma^2), sigma=10
#define MARGIN 3.0f       // 2x(6-sigma bf16 gemm err + fp16 key ulp) + slack
#define CCAP  2048        // max candidates per row
#define NBLK  12500       // 8-col blocks per row
#define NBLKS 12512       // padded row stride (u16) -> 16B aligned rows
#define NV4   1563        // uint4 loads covering 12504 blocks (last 4 masked)
#define RANK  200         // bmin rank for threshold (>= KNN guaranteed candidates)
#define NCHUNK 4          // row chunks (128 rows each) for cross-stream overlap

// ---------------- scratch (static device globals; no allocation) -------------
__device__ float g_c2[C_];
__device__ __align__(128) unsigned short g_keys16[(size_t)B_ * C_];   // 102.4 MB
__device__ __align__(128) unsigned short g_bmin[(size_t)B_ * NBLKS];  // 12.8 MB
__device__ __align__(128) __nv_bfloat16 g_Abf[(size_t)B_ * D_];
__device__ __align__(128) __nv_bfloat16 g_Bbf[(size_t)C_ * D_];
__device__ int g_cand[(size_t)B_ * CCAP];
__device__ int g_ccnt[B_];

__device__ __forceinline__ unsigned f2ord(float f) {
    unsigned b = __float_as_uint(f);
    return (b & 0x80000000u) ? ~b : (b ^ 0x80000000u);
}
__device__ __forceinline__ float ord2f(unsigned u) {
    return (u & 0x80000000u) ? __uint_as_float(u ^ 0x80000000u)
                             : __uint_as_float(~u);
}
// ordered u16 via fp16 (monotonic: x<=y -> ord(x)<=ord(y))
__device__ __forceinline__ unsigned f2ord16(float x) {
    unsigned short h = __half_as_ushort(__float2half_rn(x));
    return (h & 0x8000) ? (unsigned)(unsigned short)~h : (unsigned)(h | 0x8000);
}
__device__ __forceinline__ float ord162f(unsigned u) {
    unsigned short h = (u & 0x8000) ? (unsigned short)(u ^ 0x8000)
                                    : (unsigned short)~u;
    return __half2float(__ushort_as_half(h));
}

// ---------------- PTX helpers (base PTX only) ---------------------------------
__device__ __forceinline__ uint32_t smem_u32(const void* p) {
    uint32_t a;
    asm("{ .reg .u64 t; cvta.to.shared.u64 t, %1; cvt.u32.u64 %0, t; }"
        : "=r"(a) : "l"(p));
    return a;
}
__device__ __forceinline__ void cpa16(uint32_t dst, const void* src, int sz) {
    asm volatile("cp.async.cg.shared.global [%0], [%1], 16, %2;"
                 :: "r"(dst), "l"(src), "r"(sz));
}
__device__ __forceinline__ void cpcommit() { asm volatile("cp.async.commit_group;"); }
template <int N> __device__ __forceinline__ void cpwait() {
    asm volatile("cp.async.wait_group %0;" :: "n"(N));
}
__device__ __forceinline__ void ldsm4(uint32_t* r, uint32_t addr) {
    asm volatile("ldmatrix.sync.aligned.m8n8.x4.shared.b16 {%0,%1,%2,%3}, [%4];"
                 : "=r"(r[0]), "=r"(r[1]), "=r"(r[2]), "=r"(r[3]) : "r"(addr));
}
__device__ __forceinline__ void mma_bf16(float* d, const uint32_t* a,
                                         uint32_t b0, uint32_t b1) {
    asm volatile(
        "mma.sync.aligned.m16n8k16.row.col.f32.bf16.bf16.f32 "
        "{%0,%1,%2,%3}, {%4,%5,%6,%7}, {%8,%9}, {%0,%1,%2,%3};"
        : "+f"(d[0]), "+f"(d[1]), "+f"(d[2]), "+f"(d[3])
        : "r"(a[0]), "r"(a[1]), "r"(a[2]), "r"(a[3]), "r"(b0), "r"(b1));
}

// ---------------- kernel 1: fused convert (centres + features) ----------------
__global__ __launch_bounds__(256) void convert_kernel(const float* __restrict__ centres,
                                                      const float* __restrict__ feats) {
    const int warp = (blockIdx.x * 256 + threadIdx.x) >> 5;
    const int lane = threadIdx.x & 31;
    if (warp < C_) {
        const float4* src = (const float4*)(centres + (size_t)warp * D_);
        __nv_bfloat16* dst = g_Bbf + (size_t)warp * D_;
        float s = 0.f;
#pragma unroll
        for (int k = 0; k < 4; k++) {
            int j = lane + 32 * k;
            float4 v = src[j];
            s += v.x * v.x + v.y * v.y + v.z * v.z + v.w * v.w;
            union { __nv_bfloat16 h[4]; uint2 u; } ph;
            ph.h[0] = __float2bfloat16_rn(v.x); ph.h[1] = __float2bfloat16_rn(v.y);
            ph.h[2] = __float2bfloat16_rn(v.z); ph.h[3] = __float2bfloat16_rn(v.w);
            *(uint2*)(dst + 4 * j) = ph.u;
        }
#pragma unroll
        for (int o = 16; o; o >>= 1) s += __shfl_xor_sync(0xffffffffu, s, o);
        if (lane == 0) g_c2[warp] = s;
    } else if (warp < C_ + B_) {
        const int row = warp - C_;
        const float4* src = (const float4*)(feats + (size_t)row * D_);
        __nv_bfloat16* dst = g_Abf + (size_t)row * D_;
#pragma unroll
        for (int k = 0; k < 4; k++) {
            int j = lane + 32 * k;
            float4 v = src[j];
            union { __nv_bfloat16 h[4]; uint2 u; } ph;
            ph.h[0] = __float2bfloat16_rn(v.x); ph.h[1] = __float2bfloat16_rn(v.y);
            ph.h[2] = __float2bfloat16_rn(v.z); ph.h[3] = __float2bfloat16_rn(v.w);
            *(uint2*)(dst + 4 * j) = ph.u;
        }
    }
}

// ---------------- kernel 2: bf16 HMMA GEMM, u16 keys + 8-col block minima -----
// One 128-row chunk per launch (m0 = mbase); grid.x = 782 c-tiles.
#define GSTAGE_BYTES 32768
#define GSMEM (1024 + 3 * GSTAGE_BYTES)
__global__ void __launch_bounds__(256, 2) gemm_kernel(int mbase) {
    extern __shared__ char smem[];
    float* c2s = (float*)smem;
    const uint32_t sb = smem_u32(smem);
    const int t = threadIdx.x;
    const int m0 = mbase;
    const int c0 = blockIdx.x * 128;
    const int lane = t & 31, wid = t >> 5;
    const int wm = wid & 3, wn = wid >> 2;

    if (t < 128) { int c = c0 + t; c2s[t] = (c < C_) ? g_c2[c] : 0.f; }

    auto load_tile = [&](int kt, int buf) {
        const uint32_t sA = sb + 1024 + buf * GSTAGE_BYTES;
        const uint32_t sB = sA + 16384;
        const __nv_bfloat16* gA = g_Abf + (size_t)m0 * D_ + kt * 64;
        const __nv_bfloat16* gB = g_Bbf + (size_t)c0 * D_ + kt * 64;
#pragma unroll
        for (int i = 0; i < 4; i++) {
            int idx = t + i * 256;
            int r = idx >> 3, c = idx & 7;
            cpa16(sA + r * 128 + ((c ^ (r & 7)) << 4),
                  gA + (size_t)r * D_ + c * 8, 16);
        }
#pragma unroll
        for (int i = 0; i < 4; i++) {
            int idx = t + i * 256;
            int r = idx >> 3, c = idx & 7;
            int gr = c0 + r;
            int sz = (gr < C_) ? 16 : 0;
            const __nv_bfloat16* src = gB + (size_t)((gr < C_) ? r : 0) * D_ + c * 8;
            cpa16(sB + r * 128 + ((c ^ (r & 7)) << 4), src, sz);
        }
        cpcommit();
    };

    float acc[2][8][4];
#pragma unroll
    for (int i = 0; i < 2; i++)
#pragma unroll
        for (int j = 0; j < 8; j++)
#pragma unroll
            for (int q = 0; q < 4; q++) acc[i][j][q] = 0.f;

    load_tile(0, 0);
    load_tile(1, 1);

#pragma unroll 1
    for (int kt = 0; kt < 8; kt++) {
        const int buf = kt % 3;
        if (kt == 7) cpwait<0>(); else cpwait<1>();
        __syncthreads();
        if (kt + 2 < 8) load_tile(kt + 2, (kt + 2) % 3);
        const uint32_t sA = sb + 1024 + buf * GSTAGE_BYTES;
        const uint32_t sB = sA + 16384;
#pragma unroll
        for (int kk = 0; kk < 4; kk++) {
            uint32_t a[2][4], b[4][4];
#pragma unroll
            for (int mt = 0; mt < 2; mt++) {
                int r = wm * 32 + mt * 16 + (lane & 15);
                int ch = kk * 2 + (lane >> 4);
                ldsm4(a[mt], sA + r * 128 + ((ch ^ (r & 7)) << 4));
            }
#pragma unroll
            for (int nt = 0; nt < 4; nt++) {
                int r = wn * 64 + nt * 16 + ((lane >> 4) << 3) + (lane & 7);
                int ch = kk * 2 + ((lane >> 3) & 1);
                ldsm4(b[nt], sB + r * 128 + ((ch ^ (r & 7)) << 4));
            }
#pragma unroll
            for (int mt = 0; mt < 2; mt++)
#pragma unroll
                for (int nt = 0; nt < 4; nt++) {
                    mma_bf16(acc[mt][nt * 2],     a[mt], b[nt][0], b[nt][1]);
                    mma_bf16(acc[mt][nt * 2 + 1], a[mt], b[nt][2], b[nt][3]);
                }
        }
    }

    // epilogue: u16 ordered keys + per-8-col block minima (R10 layout).
#pragma unroll
    for (int mt = 0; mt < 2; mt++) {
#pragma unroll
        for (int nt8 = 0; nt8 < 8; nt8++) {
            int lcol = wn * 64 + nt8 * 8 + (lane & 3) * 2;
            int gcol = c0 + lcol;
            if (gcol >= C_) continue;
            int grow = m0 + wm * 32 + mt * 16 + (lane >> 2);
            float a0 = c2s[lcol]     - 2.f * acc[mt][nt8][0];
            float a1 = c2s[lcol + 1] - 2.f * acc[mt][nt8][1];
            float a2 = c2s[lcol]     - 2.f * acc[mt][nt8][2];
            float a3 = c2s[lcol + 1] - 2.f * acc[mt][nt8][3];
            unsigned k0 = f2ord16(a0), k1 = f2ord16(a1);
            unsigned k2 = f2ord16(a2), k3 = f2ord16(a3);
            *(unsigned*)(g_keys16 + (size_t)grow * C_ + gcol)       = k0 | (k1 << 16);
            *(unsigned*)(g_keys16 + (size_t)(grow + 8) * C_ + gcol) = k2 | (k3 << 16);
            float m01 = fminf(a0, a1);
            float m23 = fminf(a2, a3);
            m01 = fminf(m01, __shfl_xor_sync(0xffffffffu, m01, 1));
            m01 = fminf(m01, __shfl_xor_sync(0xffffffffu, m01, 2));
            m23 = fminf(m23, __shfl_xor_sync(0xffffffffu, m23, 1));
            m23 = fminf(m23, __shfl_xor_sync(0xffffffffu, m23, 2));
            if ((lane & 3) == 0) {
                int blk = (c0 >> 3) + wn * 8 + nt8;
                g_bmin[(size_t)grow * NBLKS + blk]       = (unsigned short)f2ord16(m01);
                g_bmin[(size_t)(grow + 8) * NBLKS + blk] = (unsigned short)f2ord16(m23);
            }
        }
    }
}

// ---------------- kernel 3: block-min threshold + hierarchical collect --------
#define NWARP 16
__global__ __launch_bounds__(512) void select_kernel(int rowbase) {
    const int row = rowbase + blockIdx.x;
    __shared__ unsigned whist[NWARP][256];   // 16KB
    __shared__ unsigned hist[256];
    __shared__ unsigned sh_b1, sh_base, sh_T;
    __shared__ int sh_ncand;
    const int t = threadIdx.x;
    const int warp = t >> 5;
    const uint4* bm4 = (const uint4*)(g_bmin + (size_t)row * NBLKS);

    if (t == 0) sh_ncand = 0;
    for (int i = t; i < NWARP * 256; i += 512) ((unsigned*)whist)[i] = 0;
    __syncthreads();

    // pass A1: histogram of bmin high byte (uint4: 8 blocks per thread-iter)
    for (int i = t; i < NV4; i += 512) {
        uint4 v = bm4[i];
        if (i == NV4 - 1) { v.z = 0xFFFFFFFFu; v.w = 0xFFFFFFFFu; }  // pad blocks
        unsigned w[4] = {v.x, v.y, v.z, v.w};
#pragma unroll
        for (int q = 0; q < 4; q++) {
            atomicAdd(&whist[warp][(w[q] & 0xFFFFu) >> 8], 1u);
            atomicAdd(&whist[warp][w[q] >> 24], 1u);
        }
    }
    __syncthreads();
    if (t < 256) {
        unsigned s = 0;
#pragma unroll
        for (int w = 0; w < NWARP; w++) s += whist[w][t];
        hist[t] = s;
    }
    __syncthreads();
    if (t == 0) {
        unsigned cum = 0;
        int b = 0;
        for (; b < 255; b++) {
            if (cum + hist[b] >= (unsigned)RANK) break;
            cum += hist[b];
        }
        sh_b1 = (unsigned)b;
        sh_base = cum;
    }
    __syncthreads();
    for (int i = t; i < NWARP * 256; i += 512) ((unsigned*)whist)[i] = 0;
    __syncthreads();

    // pass A2: low-byte histogram among bmins with high byte == b1
    const unsigned b1 = sh_b1;
    for (int i = t; i < NV4; i += 512) {
        uint4 v = bm4[i];
        if (i == NV4 - 1) { v.z = 0xFFFFFFFFu; v.w = 0xFFFFFFFFu; }
        unsigned w[4] = {v.x, v.y, v.z, v.w};
#pragma unroll
        for (int q = 0; q < 4; q++) {
            unsigned lo = w[q] & 0xFFFFu, hi = w[q] >> 16;
            if ((lo >> 8) == b1) atomicAdd(&whist[warp][lo & 255u], 1u);
            if ((hi >> 8) == b1) atomicAdd(&whist[warp][hi & 255u], 1u);
        }
    }
    __syncthreads();
    if (t < 256) {
        unsigned s = 0;
#pragma unroll
        for (int w = 0; w < NWARP; w++) s += whist[w][t];
        hist[t] = s;
    }
    __syncthreads();
    if (t == 0) {
        unsigned cum = sh_base;
        int b = 0;
        for (; b < 255; b++) {
            if (cum + hist[b] >= (unsigned)RANK) break;
            cum += hist[b];
        }
        unsigned T0 = (b1 << 8) | (unsigned)b;        // rank-RANK bmin
        unsigned Tm = f2ord16(ord162f(T0) + MARGIN) + 1;
        if (Tm > 65535u) Tm = 65535u;
        sh_T = (Tm > T0) ? Tm : T0;
    }
    __syncthreads();

    // pass B: expand hit blocks into candidate list
    const unsigned T = sh_T;
    int* cand = g_cand + (size_t)row * CCAP;
    const unsigned short* keys = g_keys16 + (size_t)row * C_;
    for (int i = t; i < NV4; i += 512) {
        uint4 v = bm4[i];
        if (i == NV4 - 1) { v.z = 0xFFFFFFFFu; v.w = 0xFFFFFFFFu; }
        unsigned w[4] = {v.x, v.y, v.z, v.w};
#pragma unroll
        for (int q = 0; q < 4; q++) {
#pragma unroll
            for (int h = 0; h < 2; h++) {
                unsigned bm = (h == 0) ? (w[q] & 0xFFFFu) : (w[q] >> 16);
                if (bm <= T) {
                    int blk = i * 8 + q * 2 + h;      // < NBLK by pad masking
                    uint4 kv = *(const uint4*)(keys + blk * 8);
                    unsigned kw[4] = {kv.x, kv.y, kv.z, kv.w};
                    int col = blk * 8;
#pragma unroll
                    for (int e = 0; e < 4; e++) {
                        if ((kw[e] & 0xFFFFu) <= T) {
                            int pos = atomicAdd(&sh_ncand, 1);
                            if (pos < CCAP) cand[pos] = col + e * 2;
                        }
                        if ((kw[e] >> 16) <= T) {
                            int pos = atomicAdd(&sh_ncand, 1);
                            if (pos < CCAP) cand[pos] = col + e * 2 + 1;
                        }
                    }
                }
            }
        }
    }
    __syncthreads();
    if (t == 0) g_ccnt[row] = min(sh_ncand, CCAP);
}

// ---------------- kernel 4: exact rescore + rank-select + histogram + log -----
__global__ __launch_bounds__(512) void rescore_kernel(const float* __restrict__ features,
                                                      const float* __restrict__ centres,
                                                      const int*   __restrict__ labels,
                                                      const float* __restrict__ weight,
                                                      float* __restrict__ out,
                                                      int rowbase) {
    const int row = rowbase + blockIdx.x;
    __shared__ unsigned long long cnd[CCAP];   // 16KB
    __shared__ float f[D_];
    __shared__ float p[NCLS];
    __shared__ float red[NWARP];
    const int t = threadIdx.x;
    const int warp = t >> 5, lane = t & 31;

    for (int i = t; i < D_; i += 512) f[i] = features[(size_t)row * D_ + i];
    for (int i = t; i < NCLS; i += 512) p[i] = 0.f;
    __syncthreads();

    const int cnt = g_ccnt[row];
    const int* cand = g_cand + (size_t)row * CCAP;

    // exact fp32 d2 per candidate (warp per candidate)
    for (int ci = warp; ci < cnt; ci += NWARP) {
        int idx = cand[ci];
        const float4* c = (const float4*)(centres + (size_t)idx * D_);
        const float4* fs = (const float4*)f;
        float s = 0.f;
#pragma unroll
        for (int k = 0; k < 4; k++) {
            int j = lane + 32 * k;
            float4 cv = c[j];
            float4 fv = fs[j];
            float dx = fv.x - cv.x, dy = fv.y - cv.y;
            float dz = fv.z - cv.z, dw = fv.w - cv.w;
            s += dx * dx + dy * dy + dz * dz + dw * dw;
        }
#pragma unroll
        for (int o = 16; o; o >>= 1) s += __shfl_xor_sync(0xffffffffu, s, o);
        if (lane == 0)
            cnd[ci] = ((unsigned long long)f2ord(s) << 32) | (unsigned)idx;
    }
    __syncthreads();

    // rank-count selection (order-free; ranks unique since idx in low bits;
    // ties by ascending idx match JAX top_k order)
    for (int ci = t; ci < cnt; ci += 512) {
        unsigned long long v = cnd[ci];
        int r = 0;
        for (int q = 0; q < cnt; q++) r += (cnd[q] < v);
        if (r < KNN) {
            int idx = (int)(v & 0xffffffffull);
            float d2 = ord2f((unsigned)(v >> 32));
            float d = expf(-d2 * GCONST) * expf(weight[idx]);
            atomicAdd(&p[labels[idx]], d);
        }
    }
    __syncthreads();

    float partial = 0.f;
    for (int i = t; i < NCLS; i += 512) {
        float v = p[i];
        if (v == 0.f) v = 1e-10f;
        p[i] = v;
        partial += v;
    }
#pragma unroll
    for (int o = 16; o; o >>= 1) partial += __shfl_xor_sync(0xffffffffu, partial, o);
    if (lane == 0) red[warp] = partial;
    __syncthreads();
    if (t < 32) {
        float v = (t < NWARP) ? red[t] : 0.f;
#pragma unroll
        for (int o = 8; o; o >>= 1) v += __shfl_xor_sync(0xffffffffu, v, o);
        if (t == 0) red[0] = v;
    }
    __syncthreads();
    const float sum = red[0];
    for (int i = t; i < NCLS; i += 512)
        out[(size_t)row * NCLS + i] = logf(p[i] / sum);
}

// ---------------- launcher: chunked GEMM + cross-stream overlapped selres -----
extern "C" void kernel_launch(void* const* d_in, const int* in_sizes, int n_in,
                              void* d_out, int out_size) {
    const float* features = (const float*)d_in[0];   // [512, 512]
    const float* centres  = (const float*)d_in[1];   // [100000, 512]
    const int*   labels   = (const int*)d_in[2];     // [100000]
    const float* weight   = (const float*)d_in[3];   // [100000]
    float* out = (float*)d_out;                      // [512, 1000]

    static cudaStream_t s1 = nullptr;
    static cudaEvent_t evg[NCHUNK];
    static cudaEvent_t evDone = nullptr;
    if (s1 == nullptr) {
        cudaStreamCreateWithFlags(&s1, cudaStreamNonBlocking);
        for (int i = 0; i < NCHUNK; i++)
            cudaEventCreateWithFlags(&evg[i], cudaEventDisableTiming);
        cudaEventCreateWithFlags(&evDone, cudaEventDisableTiming);
        cudaFuncSetAttribute(gemm_kernel,
                             cudaFuncAttributeMaxDynamicSharedMemorySize, GSMEM);
    }

    convert_kernel<<<(C_ + B_ + 7) / 8, 256>>>(centres, features);

    const int gx = (C_ + 127) / 128;   // 782 c-tiles
    for (int c = 0; c < NCHUNK; c++) {
        gemm_kernel<<<gx, 256, GSMEM>>>(c * 128);
        cudaEventRecord(evg[c], 0);
        cudaStreamWaitEvent(s1, evg[c], 0);
        select_kernel<<<B_ / NCHUNK, 512, 0, s1>>>(c * (B_ / NCHUNK));
        rescore_kernel<<<B_ / NCHUNK, 512, 0, s1>>>(features, centres, labels,
                                                    weight, out, c * (B_ / NCHUNK));
    }
    cudaEventRecord(evDone, s1);
    cudaStreamWaitEvent(0, evDone, 0);
}

// round 14
// speedup vs baseline: 1.1465x; 1.1465x over previous
#include <cuda_runtime.h>
#include <cuda_bf16.h>
#include <cuda_fp16.h>
#include <math.h>
#include <stdint.h>

#define B_    512
#define D_    512
#define C_    100000
#define KNN   200
#define NCLS  1000
#define GCONST 0.005f     // 1/(2*sigma^2), sigma=10
#define MARGIN 3.0f       // 2x(6-sigma bf16 gemm err + fp16 key ulp) + slack
#define CCAP  2048        // max candidates per row
#define NBLK  12500       // 8-col blocks per row
#define NBLKS 12512       // padded row stride (u16) -> 16B aligned rows
#define NV4   1563        // uint4 loads covering 12504 blocks (last 4 masked)
#define RANK  200         // bmin rank for threshold (>= KNN guaranteed candidates)

// ---------------- scratch (static device globals; no allocation) -------------
__device__ float g_c2[C_];
__device__ __align__(128) unsigned short g_keys16[(size_t)B_ * C_];   // 102.4 MB
__device__ __align__(128) unsigned short g_bmin[(size_t)B_ * NBLKS];  // 12.8 MB
__device__ __align__(128) __nv_bfloat16 g_Abf[(size_t)B_ * D_];
__device__ __align__(128) __nv_bfloat16 g_Bbf[(size_t)C_ * D_];
__device__ int g_cand[(size_t)B_ * CCAP];
__device__ int g_ccnt[B_];

__device__ __forceinline__ unsigned f2ord(float f) {
    unsigned b = __float_as_uint(f);
    return (b & 0x80000000u) ? ~b : (b ^ 0x80000000u);
}
__device__ __forceinline__ float ord2f(unsigned u) {
    return (u & 0x80000000u) ? __uint_as_float(u ^ 0x80000000u)
                             : __uint_as_float(~u);
}
// ordered u16 via fp16 (monotonic: x<=y -> ord(x)<=ord(y))
__device__ __forceinline__ unsigned f2ord16(float x) {
    unsigned short h = __half_as_ushort(__float2half_rn(x));
    return (h & 0x8000) ? (unsigned)(unsigned short)~h : (unsigned)(h | 0x8000);
}
__device__ __forceinline__ float ord162f(unsigned u) {
    unsigned short h = (u & 0x8000) ? (unsigned short)(u ^ 0x8000)
                                    : (unsigned short)~u;
    return __half2float(__ushort_as_half(h));
}

// ---------------- PTX helpers (base PTX only) ---------------------------------
__device__ __forceinline__ uint32_t smem_u32(const void* p) {
    uint32_t a;
    asm("{ .reg .u64 t; cvta.to.shared.u64 t, %1; cvt.u32.u64 %0, t; }"
        : "=r"(a) : "l"(p));
    return a;
}
__device__ __forceinline__ void cpa16(uint32_t dst, const void* src, int sz) {
    asm volatile("cp.async.cg.shared.global [%0], [%1], 16, %2;"
                 :: "r"(dst), "l"(src), "r"(sz));
}
__device__ __forceinline__ void cpcommit() { asm volatile("cp.async.commit_group;"); }
template <int N> __device__ __forceinline__ void cpwait() {
    asm volatile("cp.async.wait_group %0;" :: "n"(N));
}
__device__ __forceinline__ void ldsm4(uint32_t* r, uint32_t addr) {
    asm volatile("ldmatrix.sync.aligned.m8n8.x4.shared.b16 {%0,%1,%2,%3}, [%4];"
                 : "=r"(r[0]), "=r"(r[1]), "=r"(r[2]), "=r"(r[3]) : "r"(addr));
}
__device__ __forceinline__ void mma_bf16(float* d, const uint32_t* a,
                                         uint32_t b0, uint32_t b1) {
    asm volatile(
        "mma.sync.aligned.m16n8k16.row.col.f32.bf16.bf16.f32 "
        "{%0,%1,%2,%3}, {%4,%5,%6,%7}, {%8,%9}, {%0,%1,%2,%3};"
        : "+f"(d[0]), "+f"(d[1]), "+f"(d[2]), "+f"(d[3])
        : "r"(a[0]), "r"(a[1]), "r"(a[2]), "r"(a[3]), "r"(b0), "r"(b1));
}

// ---------------- kernel 1: fused convert (centres + features) ----------------
__global__ __launch_bounds__(256) void convert_kernel(const float* __restrict__ centres,
                                                      const float* __restrict__ feats) {
    const int warp = (blockIdx.x * 256 + threadIdx.x) >> 5;
    const int lane = threadIdx.x & 31;
    if (warp < C_) {
        const float4* src = (const float4*)(centres + (size_t)warp * D_);
        __nv_bfloat16* dst = g_Bbf + (size_t)warp * D_;
        float s = 0.f;
#pragma unroll
        for (int k = 0; k < 4; k++) {
            int j = lane + 32 * k;
            float4 v = src[j];
            s += v.x * v.x + v.y * v.y + v.z * v.z + v.w * v.w;
            union { __nv_bfloat16 h[4]; uint2 u; } ph;
            ph.h[0] = __float2bfloat16_rn(v.x); ph.h[1] = __float2bfloat16_rn(v.y);
            ph.h[2] = __float2bfloat16_rn(v.z); ph.h[3] = __float2bfloat16_rn(v.w);
            *(uint2*)(dst + 4 * j) = ph.u;
        }
#pragma unroll
        for (int o = 16; o; o >>= 1) s += __shfl_xor_sync(0xffffffffu, s, o);
        if (lane == 0) g_c2[warp] = s;
    } else if (warp < C_ + B_) {
        const int row = warp - C_;
        const float4* src = (const float4*)(feats + (size_t)row * D_);
        __nv_bfloat16* dst = g_Abf + (size_t)row * D_;
#pragma unroll
        for (int k = 0; k < 4; k++) {
            int j = lane + 32 * k;
            float4 v = src[j];
            union { __nv_bfloat16 h[4]; uint2 u; } ph;
            ph.h[0] = __float2bfloat16_rn(v.x); ph.h[1] = __float2bfloat16_rn(v.y);
            ph.h[2] = __float2bfloat16_rn(v.z); ph.h[3] = __float2bfloat16_rn(v.w);
            *(uint2*)(dst + 4 * j) = ph.u;
        }
    }
}

// ---------------- kernel 2: bf16 HMMA GEMM 128x256 tile, keys + block minima --
// 512 threads (16 warps = 4 wm x 4 wn, warp tile 32x64), BK=64, 3-stage.
// Stage = A 16KB + B 32KB = 48KB; GSMEM = 1KB c2s + 144KB.
#define GSTAGE_BYTES 49152
#define GSMEM (1024 + 3 * GSTAGE_BYTES)
__global__ void __launch_bounds__(512, 1) gemm_kernel() {
    extern __shared__ char smem[];
    float* c2s = (float*)smem;
    const uint32_t sb = smem_u32(smem);
    const int t = threadIdx.x;
    const int m0 = blockIdx.x * 128;
    const int c0 = blockIdx.y * 256;
    const int lane = t & 31, wid = t >> 5;
    const int wm = wid & 3, wn = wid >> 2;

    if (t < 256) { int c = c0 + t; c2s[t] = (c < C_) ? g_c2[c] : 0.f; }

    auto load_tile = [&](int kt, int buf) {
        const uint32_t sA = sb + 1024 + buf * GSTAGE_BYTES;
        const uint32_t sB = sA + 16384;
        const __nv_bfloat16* gA = g_Abf + (size_t)m0 * D_ + kt * 64;
        const __nv_bfloat16* gB = g_Bbf + (size_t)c0 * D_ + kt * 64;
#pragma unroll
        for (int i = 0; i < 2; i++) {             // A: 1024 16B chunks
            int idx = t + i * 512;
            int r = idx >> 3, c = idx & 7;
            cpa16(sA + r * 128 + ((c ^ (r & 7)) << 4),
                  gA + (size_t)r * D_ + c * 8, 16);
        }
#pragma unroll
        for (int i = 0; i < 4; i++) {             // B: 2048 16B chunks (256 rows)
            int idx = t + i * 512;
            int r = idx >> 3, c = idx & 7;
            int gr = c0 + r;
            int sz = (gr < C_) ? 16 : 0;
            const __nv_bfloat16* src = gB + (size_t)((gr < C_) ? r : 0) * D_ + c * 8;
            cpa16(sB + r * 128 + ((c ^ (r & 7)) << 4), src, sz);
        }
        cpcommit();
    };

    float acc[2][8][4];
#pragma unroll
    for (int i = 0; i < 2; i++)
#pragma unroll
        for (int j = 0; j < 8; j++)
#pragma unroll
            for (int q = 0; q < 4; q++) acc[i][j][q] = 0.f;

    load_tile(0, 0);
    load_tile(1, 1);

#pragma unroll 1
    for (int kt = 0; kt < 8; kt++) {
        const int buf = kt % 3;
        if (kt == 7) cpwait<0>(); else cpwait<1>();
        __syncthreads();
        if (kt + 2 < 8) load_tile(kt + 2, (kt + 2) % 3);
        const uint32_t sA = sb + 1024 + buf * GSTAGE_BYTES;
        const uint32_t sB = sA + 16384;
#pragma unroll
        for (int kk = 0; kk < 4; kk++) {
            uint32_t a[2][4], b[4][4];
#pragma unroll
            for (int mt = 0; mt < 2; mt++) {
                int r = wm * 32 + mt * 16 + (lane & 15);
                int ch = kk * 2 + (lane >> 4);
                ldsm4(a[mt], sA + r * 128 + ((ch ^ (r & 7)) << 4));
            }
#pragma unroll
            for (int nt = 0; nt < 4; nt++) {
                int r = wn * 64 + nt * 16 + ((lane >> 4) << 3) + (lane & 7);
                int ch = kk * 2 + ((lane >> 3) & 1);
                ldsm4(b[nt], sB + r * 128 + ((ch ^ (r & 7)) << 4));
            }
#pragma unroll
            for (int mt = 0; mt < 2; mt++)
#pragma unroll
                for (int nt = 0; nt < 4; nt++) {
                    mma_bf16(acc[mt][nt * 2],     a[mt], b[nt][0], b[nt][1]);
                    mma_bf16(acc[mt][nt * 2 + 1], a[mt], b[nt][2], b[nt][3]);
                }
        }
    }

    // epilogue: u16 ordered keys + per-8-col block minima (R10 layout).
#pragma unroll
    for (int mt = 0; mt < 2; mt++) {
#pragma unroll
        for (int nt8 = 0; nt8 < 8; nt8++) {
            int lcol = wn * 64 + nt8 * 8 + (lane & 3) * 2;
            int gcol = c0 + lcol;
            if (gcol >= C_) continue;
            int grow = m0 + wm * 32 + mt * 16 + (lane >> 2);
            float a0 = c2s[lcol]     - 2.f * acc[mt][nt8][0];
            float a1 = c2s[lcol + 1] - 2.f * acc[mt][nt8][1];
            float a2 = c2s[lcol]     - 2.f * acc[mt][nt8][2];
            float a3 = c2s[lcol + 1] - 2.f * acc[mt][nt8][3];
            unsigned k0 = f2ord16(a0), k1 = f2ord16(a1);
            unsigned k2 = f2ord16(a2), k3 = f2ord16(a3);
            *(unsigned*)(g_keys16 + (size_t)grow * C_ + gcol)       = k0 | (k1 << 16);
            *(unsigned*)(g_keys16 + (size_t)(grow + 8) * C_ + gcol) = k2 | (k3 << 16);
            float m01 = fminf(a0, a1);
            float m23 = fminf(a2, a3);
            m01 = fminf(m01, __shfl_xor_sync(0xffffffffu, m01, 1));
            m01 = fminf(m01, __shfl_xor_sync(0xffffffffu, m01, 2));
            m23 = fminf(m23, __shfl_xor_sync(0xffffffffu, m23, 1));
            m23 = fminf(m23, __shfl_xor_sync(0xffffffffu, m23, 2));
            if ((lane & 3) == 0) {
                int blk = (c0 >> 3) + wn * 8 + nt8;
                g_bmin[(size_t)grow * NBLKS + blk]       = (unsigned short)f2ord16(m01);
                g_bmin[(size_t)(grow + 8) * NBLKS + blk] = (unsigned short)f2ord16(m23);
            }
        }
    }
}

// ---------------- kernel 3: block-min threshold + hierarchical collect --------
#define NWARP 16
__global__ __launch_bounds__(512) void select_kernel() {
    const int row = blockIdx.x;
    __shared__ unsigned whist[NWARP][256];   // 16KB
    __shared__ unsigned hist[256];
    __shared__ unsigned sh_b1, sh_base, sh_T;
    __shared__ int sh_ncand;
    const int t = threadIdx.x;
    const int warp = t >> 5;
    const uint4* bm4 = (const uint4*)(g_bmin + (size_t)row * NBLKS);

    if (t == 0) sh_ncand = 0;
    for (int i = t; i < NWARP * 256; i += 512) ((unsigned*)whist)[i] = 0;
    __syncthreads();

    // pass A1: histogram of bmin high byte (uint4: 8 blocks per thread-iter)
    for (int i = t; i < NV4; i += 512) {
        uint4 v = bm4[i];
        if (i == NV4 - 1) { v.z = 0xFFFFFFFFu; v.w = 0xFFFFFFFFu; }  // pad blocks
        unsigned w[4] = {v.x, v.y, v.z, v.w};
#pragma unroll
        for (int q = 0; q < 4; q++) {
            atomicAdd(&whist[warp][(w[q] & 0xFFFFu) >> 8], 1u);
            atomicAdd(&whist[warp][w[q] >> 24], 1u);
        }
    }
    __syncthreads();
    if (t < 256) {
        unsigned s = 0;
#pragma unroll
        for (int w = 0; w < NWARP; w++) s += whist[w][t];
        hist[t] = s;
    }
    __syncthreads();
    if (t == 0) {
        unsigned cum = 0;
        int b = 0;
        for (; b < 255; b++) {
            if (cum + hist[b] >= (unsigned)RANK) break;
            cum += hist[b];
        }
        sh_b1 = (unsigned)b;
        sh_base = cum;
    }
    __syncthreads();
    for (int i = t; i < NWARP * 256; i += 512) ((unsigned*)whist)[i] = 0;
    __syncthreads();

    // pass A2: low-byte histogram among bmins with high byte == b1
    const unsigned b1 = sh_b1;
    for (int i = t; i < NV4; i += 512) {
        uint4 v = bm4[i];
        if (i == NV4 - 1) { v.z = 0xFFFFFFFFu; v.w = 0xFFFFFFFFu; }
        unsigned w[4] = {v.x, v.y, v.z, v.w};
#pragma unroll
        for (int q = 0; q < 4; q++) {
            unsigned lo = w[q] & 0xFFFFu, hi = w[q] >> 16;
            if ((lo >> 8) == b1) atomicAdd(&whist[warp][lo & 255u], 1u);
            if ((hi >> 8) == b1) atomicAdd(&whist[warp][hi & 255u], 1u);
        }
    }
    __syncthreads();
    if (t < 256) {
        unsigned s = 0;
#pragma unroll
        for (int w = 0; w < NWARP; w++) s += whist[w][t];
        hist[t] = s;
    }
    __syncthreads();
    if (t == 0) {
        unsigned cum = sh_base;
        int b = 0;
        for (; b < 255; b++) {
            if (cum + hist[b] >= (unsigned)RANK) break;
            cum += hist[b];
        }
        unsigned T0 = (b1 << 8) | (unsigned)b;        // rank-RANK bmin
        unsigned Tm = f2ord16(ord162f(T0) + MARGIN) + 1;
        if (Tm > 65535u) Tm = 65535u;
        sh_T = (Tm > T0) ? Tm : T0;
    }
    __syncthreads();

    // pass B: expand hit blocks into candidate list
    const unsigned T = sh_T;
    int* cand = g_cand + (size_t)row * CCAP;
    const unsigned short* keys = g_keys16 + (size_t)row * C_;
    for (int i = t; i < NV4; i += 512) {
        uint4 v = bm4[i];
        if (i == NV4 - 1) { v.z = 0xFFFFFFFFu; v.w = 0xFFFFFFFFu; }
        unsigned w[4] = {v.x, v.y, v.z, v.w};
#pragma unroll
        for (int q = 0; q < 4; q++) {
#pragma unroll
            for (int h = 0; h < 2; h++) {
                unsigned bm = (h == 0) ? (w[q] & 0xFFFFu) : (w[q] >> 16);
                if (bm <= T) {
                    int blk = i * 8 + q * 2 + h;      // < NBLK by pad masking
                    uint4 kv = *(const uint4*)(keys + blk * 8);
                    unsigned kw[4] = {kv.x, kv.y, kv.z, kv.w};
                    int col = blk * 8;
#pragma unroll
                    for (int e = 0; e < 4; e++) {
                        if ((kw[e] & 0xFFFFu) <= T) {
                            int pos = atomicAdd(&sh_ncand, 1);
                            if (pos < CCAP) cand[pos] = col + e * 2;
                        }
                        if ((kw[e] >> 16) <= T) {
                            int pos = atomicAdd(&sh_ncand, 1);
                            if (pos < CCAP) cand[pos] = col + e * 2 + 1;
                        }
                    }
                }
            }
        }
    }
    __syncthreads();
    if (t == 0) g_ccnt[row] = min(sh_ncand, CCAP);
}

// ---------------- kernel 4: exact rescore + rank-select + histogram + log -----
__global__ __launch_bounds__(512) void rescore_kernel(const float* __restrict__ features,
                                                      const float* __restrict__ centres,
                                                      const int*   __restrict__ labels,
                                                      const float* __restrict__ weight,
                                                      float* __restrict__ out) {
    const int row = blockIdx.x;
    __shared__ unsigned long long cnd[CCAP];   // 16KB
    __shared__ float f[D_];
    __shared__ float p[NCLS];
    __shared__ float red[NWARP];
    const int t = threadIdx.x;
    const int warp = t >> 5, lane = t & 31;

    for (int i = t; i < D_; i += 512) f[i] = features[(size_t)row * D_ + i];
    for (int i = t; i < NCLS; i += 512) p[i] = 0.f;
    __syncthreads();

    const int cnt = g_ccnt[row];
    const int* cand = g_cand + (size_t)row * CCAP;

    // exact fp32 d2 per candidate (warp per candidate)
    for (int ci = warp; ci < cnt; ci += NWARP) {
        int idx = cand[ci];
        const float4* c = (const float4*)(centres + (size_t)idx * D_);
        const float4* fs = (const float4*)f;
        float s = 0.f;
#pragma unroll
        for (int k = 0; k < 4; k++) {
            int j = lane + 32 * k;
            float4 cv = c[j];
            float4 fv = fs[j];
            float dx = fv.x - cv.x, dy = fv.y - cv.y;
            float dz = fv.z - cv.z, dw = fv.w - cv.w;
            s += dx * dx + dy * dy + dz * dz + dw * dw;
        }
#pragma unroll
        for (int o = 16; o; o >>= 1) s += __shfl_xor_sync(0xffffffffu, s, o);
        if (lane == 0)
            cnd[ci] = ((unsigned long long)f2ord(s) << 32) | (unsigned)idx;
    }
    __syncthreads();

    // rank-count selection (order-free; ranks unique since idx in low bits;
    // ties by ascending idx match JAX top_k order)
    for (int ci = t; ci < cnt; ci += 512) {
        unsigned long long v = cnd[ci];
        int r = 0;
        for (int q = 0; q < cnt; q++) r += (cnd[q] < v);
        if (r < KNN) {
            int idx = (int)(v & 0xffffffffull);
            float d2 = ord2f((unsigned)(v >> 32));
            float d = expf(-d2 * GCONST) * expf(weight[idx]);
            atomicAdd(&p[labels[idx]], d);
        }
    }
    __syncthreads();

    float partial = 0.f;
    for (int i = t; i < NCLS; i += 512) {
        float v = p[i];
        if (v == 0.f) v = 1e-10f;
        p[i] = v;
        partial += v;
    }
#pragma unroll
    for (int o = 16; o; o >>= 1) partial += __shfl_xor_sync(0xffffffffu, partial, o);
    if (lane == 0) red[warp] = partial;
    __syncthreads();
    if (t < 32) {
        float v = (t < NWARP) ? red[t] : 0.f;
#pragma unroll
        for (int o = 8; o; o >>= 1) v += __shfl_xor_sync(0xffffffffu, v, o);
        if (t == 0) red[0] = v;
    }
    __syncthreads();
    const float sum = red[0];
    for (int i = t; i < NCLS; i += 512)
        out[(size_t)row * NCLS + i] = logf(p[i] / sum);
}

// ---------------- launcher ----------------------------------------------------
extern "C" void kernel_launch(void* const* d_in, const int* in_sizes, int n_in,
                              void* d_out, int out_size) {
    const float* features = (const float*)d_in[0];   // [512, 512]
    const float* centres  = (const float*)d_in[1];   // [100000, 512]
    const int*   labels   = (const int*)d_in[2];     // [100000]
    const float* weight   = (const float*)d_in[3];   // [100000]
    float* out = (float*)d_out;                      // [512, 1000]

    cudaFuncSetAttribute(gemm_kernel,
                         cudaFuncAttributeMaxDynamicSharedMemorySize, GSMEM);

    convert_kernel<<<(C_ + B_ + 7) / 8, 256>>>(centres, features);

    dim3 gg(B_ / 128, (C_ + 255) / 256);   // x = m-tile (fast), y = c-tile
    gemm_kernel<<<gg, 512, GSMEM>>>();

    select_kernel<<<B_, 512>>>();

    rescore_kernel<<<B_, 512>>>(features, centres, labels, weight, out);
}

// round 15
// speedup vs baseline: 1.3452x; 1.1732x over previous
#include <cuda_runtime.h>
#include <cuda_bf16.h>
#include <cuda_fp16.h>
#include <math.h>
#include <stdint.h>

#define B_    512
#define D_    512
#define C_    100000
#define KNN   200
#define NCLS  1000
#define GCONST 0.005f     // 1/(2*sigma^2), sigma=10
#define MARGIN 3.0f       // 2x(6-sigma bf16 gemm err + fp16 key ulp) + slack
#define CCAP  2048        // max candidates per row
#define NBLK  12500       // 8-col blocks per row
#define NBLKS 12512       // padded row stride (u16) -> 16B aligned rows
#define NV4   1563        // uint4 loads covering 12504 blocks (last 4 masked)
#define RANK  200         // bmin rank for threshold (>= KNN guaranteed candidates)

// ---------------- scratch (static device globals; no allocation) -------------
__device__ float g_c2[C_];
__device__ __align__(128) unsigned short g_keys16[(size_t)B_ * C_];   // 102.4 MB
__device__ __align__(128) unsigned short g_bmin[(size_t)B_ * NBLKS];  // 12.8 MB
__device__ __align__(128) __nv_bfloat16 g_Abf[(size_t)B_ * D_];
__device__ __align__(128) __nv_bfloat16 g_Bbf[(size_t)C_ * D_];
__device__ int g_cand[(size_t)B_ * CCAP];
__device__ int g_ccnt[B_];

__device__ __forceinline__ unsigned f2ord(float f) {
    unsigned b = __float_as_uint(f);
    return (b & 0x80000000u) ? ~b : (b ^ 0x80000000u);
}
__device__ __forceinline__ float ord2f(unsigned u) {
    return (u & 0x80000000u) ? __uint_as_float(u ^ 0x80000000u)
                             : __uint_as_float(~u);
}
// ordered u16 via fp16 (monotonic: x<=y -> ord(x)<=ord(y))
__device__ __forceinline__ unsigned f2ord16(float x) {
    unsigned short h = __half_as_ushort(__float2half_rn(x));
    return (h & 0x8000) ? (unsigned)(unsigned short)~h : (unsigned)(h | 0x8000);
}
__device__ __forceinline__ float ord162f(unsigned u) {
    unsigned short h = (u & 0x8000) ? (unsigned short)(u ^ 0x8000)
                                    : (unsigned short)~u;
    return __half2float(__ushort_as_half(h));
}

// ---------------- PTX helpers (base PTX only) ---------------------------------
__device__ __forceinline__ uint32_t smem_u32(const void* p) {
    uint32_t a;
    asm("{ .reg .u64 t; cvta.to.shared.u64 t, %1; cvt.u32.u64 %0, t; }"
        : "=r"(a) : "l"(p));
    return a;
}
__device__ __forceinline__ void cpa16(uint32_t dst, const void* src, int sz) {
    asm volatile("cp.async.cg.shared.global [%0], [%1], 16, %2;"
                 :: "r"(dst), "l"(src), "r"(sz));
}
__device__ __forceinline__ void cpcommit() { asm volatile("cp.async.commit_group;"); }
template <int N> __device__ __forceinline__ void cpwait() {
    asm volatile("cp.async.wait_group %0;" :: "n"(N));
}
__device__ __forceinline__ void ldsm4(uint32_t* r, uint32_t addr) {
    asm volatile("ldmatrix.sync.aligned.m8n8.x4.shared.b16 {%0,%1,%2,%3}, [%4];"
                 : "=r"(r[0]), "=r"(r[1]), "=r"(r[2]), "=r"(r[3]) : "r"(addr));
}
__device__ __forceinline__ void mma_bf16(float* d, const uint32_t* a,
                                         uint32_t b0, uint32_t b1) {
    asm volatile(
        "mma.sync.aligned.m16n8k16.row.col.f32.bf16.bf16.f32 "
        "{%0,%1,%2,%3}, {%4,%5,%6,%7}, {%8,%9}, {%0,%1,%2,%3};"
        : "+f"(d[0]), "+f"(d[1]), "+f"(d[2]), "+f"(d[3])
        : "r"(a[0]), "r"(a[1]), "r"(a[2]), "r"(a[3]), "r"(b0), "r"(b1));
}

// ---------------- kernel 1: fused convert (centres + features) ----------------
__global__ __launch_bounds__(256) void convert_kernel(const float* __restrict__ centres,
                                                      const float* __restrict__ feats) {
    const int warp = (blockIdx.x * 256 + threadIdx.x) >> 5;
    const int lane = threadIdx.x & 31;
    if (warp < C_) {
        const float4* src = (const float4*)(centres + (size_t)warp * D_);
        __nv_bfloat16* dst = g_Bbf + (size_t)warp * D_;
        float s = 0.f;
#pragma unroll
        for (int k = 0; k < 4; k++) {
            int j = lane + 32 * k;
            float4 v = src[j];
            s += v.x * v.x + v.y * v.y + v.z * v.z + v.w * v.w;
            union { __nv_bfloat16 h[4]; uint2 u; } ph;
            ph.h[0] = __float2bfloat16_rn(v.x); ph.h[1] = __float2bfloat16_rn(v.y);
            ph.h[2] = __float2bfloat16_rn(v.z); ph.h[3] = __float2bfloat16_rn(v.w);
            *(uint2*)(dst + 4 * j) = ph.u;
        }
#pragma unroll
        for (int o = 16; o; o >>= 1) s += __shfl_xor_sync(0xffffffffu, s, o);
        if (lane == 0) g_c2[warp] = s;
    } else if (warp < C_ + B_) {
        const int row = warp - C_;
        const float4* src = (const float4*)(feats + (size_t)row * D_);
        __nv_bfloat16* dst = g_Abf + (size_t)row * D_;
#pragma unroll
        for (int k = 0; k < 4; k++) {
            int j = lane + 32 * k;
            float4 v = src[j];
            union { __nv_bfloat16 h[4]; uint2 u; } ph;
            ph.h[0] = __float2bfloat16_rn(v.x); ph.h[1] = __float2bfloat16_rn(v.y);
            ph.h[2] = __float2bfloat16_rn(v.z); ph.h[3] = __float2bfloat16_rn(v.w);
            *(uint2*)(dst + 4 * j) = ph.u;
        }
    }
}

// ---------------- kernel 2: bf16 HMMA GEMM, u16 keys + 8-col block minima -----
#define GSTAGE_BYTES 32768
#define GSMEM (1024 + 3 * GSTAGE_BYTES)
__global__ void __launch_bounds__(256, 2) gemm_kernel() {
    extern __shared__ char smem[];
    float* c2s = (float*)smem;
    const uint32_t sb = smem_u32(smem);
    const int t = threadIdx.x;
    const int m0 = blockIdx.x * 128;
    const int c0 = blockIdx.y * 128;
    const int lane = t & 31, wid = t >> 5;
    const int wm = wid & 3, wn = wid >> 2;

    if (t < 128) { int c = c0 + t; c2s[t] = (c < C_) ? g_c2[c] : 0.f; }

    auto load_tile = [&](int kt, int buf) {
        const uint32_t sA = sb + 1024 + buf * GSTAGE_BYTES;
        const uint32_t sB = sA + 16384;
        const __nv_bfloat16* gA = g_Abf + (size_t)m0 * D_ + kt * 64;
        const __nv_bfloat16* gB = g_Bbf + (size_t)c0 * D_ + kt * 64;
#pragma unroll
        for (int i = 0; i < 4; i++) {
            int idx = t + i * 256;
            int r = idx >> 3, c = idx & 7;
            cpa16(sA + r * 128 + ((c ^ (r & 7)) << 4),
                  gA + (size_t)r * D_ + c * 8, 16);
        }
#pragma unroll
        for (int i = 0; i < 4; i++) {
            int idx = t + i * 256;
            int r = idx >> 3, c = idx & 7;
            int gr = c0 + r;
            int sz = (gr < C_) ? 16 : 0;
            const __nv_bfloat16* src = gB + (size_t)((gr < C_) ? r : 0) * D_ + c * 8;
            cpa16(sB + r * 128 + ((c ^ (r & 7)) << 4), src, sz);
        }
        cpcommit();
    };

    float acc[2][8][4];
#pragma unroll
    for (int i = 0; i < 2; i++)
#pragma unroll
        for (int j = 0; j < 8; j++)
#pragma unroll
            for (int q = 0; q < 4; q++) acc[i][j][q] = 0.f;

    load_tile(0, 0);
    load_tile(1, 1);

#pragma unroll 1
    for (int kt = 0; kt < 8; kt++) {
        const int buf = kt % 3;
        if (kt == 7) cpwait<0>(); else cpwait<1>();
        __syncthreads();
        if (kt + 2 < 8) load_tile(kt + 2, (kt + 2) % 3);
        const uint32_t sA = sb + 1024 + buf * GSTAGE_BYTES;
        const uint32_t sB = sA + 16384;
#pragma unroll
        for (int kk = 0; kk < 4; kk++) {
            uint32_t a[2][4], b[4][4];
#pragma unroll
            for (int mt = 0; mt < 2; mt++) {
                int r = wm * 32 + mt * 16 + (lane & 15);
                int ch = kk * 2 + (lane >> 4);
                ldsm4(a[mt], sA + r * 128 + ((ch ^ (r & 7)) << 4));
            }
#pragma unroll
            for (int nt = 0; nt < 4; nt++) {
                int r = wn * 64 + nt * 16 + ((lane >> 4) << 3) + (lane & 7);
                int ch = kk * 2 + ((lane >> 3) & 1);
                ldsm4(b[nt], sB + r * 128 + ((ch ^ (r & 7)) << 4));
            }
#pragma unroll
            for (int mt = 0; mt < 2; mt++)
#pragma unroll
                for (int nt = 0; nt < 4; nt++) {
                    mma_bf16(acc[mt][nt * 2],     a[mt], b[nt][0], b[nt][1]);
                    mma_bf16(acc[mt][nt * 2 + 1], a[mt], b[nt][2], b[nt][3]);
                }
        }
    }

    // epilogue: u16 ordered keys + per-8-col block minima.
#pragma unroll
    for (int mt = 0; mt < 2; mt++) {
#pragma unroll
        for (int nt8 = 0; nt8 < 8; nt8++) {
            int lcol = wn * 64 + nt8 * 8 + (lane & 3) * 2;
            int gcol = c0 + lcol;
            if (gcol >= C_) continue;
            int grow = m0 + wm * 32 + mt * 16 + (lane >> 2);
            float a0 = c2s[lcol]     - 2.f * acc[mt][nt8][0];
            float a1 = c2s[lcol + 1] - 2.f * acc[mt][nt8][1];
            float a2 = c2s[lcol]     - 2.f * acc[mt][nt8][2];
            float a3 = c2s[lcol + 1] - 2.f * acc[mt][nt8][3];
            unsigned k0 = f2ord16(a0), k1 = f2ord16(a1);
            unsigned k2 = f2ord16(a2), k3 = f2ord16(a3);
            *(unsigned*)(g_keys16 + (size_t)grow * C_ + gcol)       = k0 | (k1 << 16);
            *(unsigned*)(g_keys16 + (size_t)(grow + 8) * C_ + gcol) = k2 | (k3 << 16);
            float m01 = fminf(a0, a1);
            float m23 = fminf(a2, a3);
            m01 = fminf(m01, __shfl_xor_sync(0xffffffffu, m01, 1));
            m01 = fminf(m01, __shfl_xor_sync(0xffffffffu, m01, 2));
            m23 = fminf(m23, __shfl_xor_sync(0xffffffffu, m23, 1));
            m23 = fminf(m23, __shfl_xor_sync(0xffffffffu, m23, 2));
            if ((lane & 3) == 0) {
                int blk = (c0 >> 3) + wn * 8 + nt8;
                g_bmin[(size_t)grow * NBLKS + blk]       = (unsigned short)f2ord16(m01);
                g_bmin[(size_t)(grow + 8) * NBLKS + blk] = (unsigned short)f2ord16(m23);
            }
        }
    }
}

// ---------------- kernel 3: block-min threshold + hierarchical collect --------
#define NWARP 16
__global__ __launch_bounds__(512) void select_kernel() {
    const int row = blockIdx.x;
    __shared__ unsigned whist[NWARP][256];   // 16KB
    __shared__ unsigned hist[256];
    __shared__ unsigned sh_b1, sh_base, sh_T;
    __shared__ int sh_ncand;
    const int t = threadIdx.x;
    const int warp = t >> 5;
    const uint4* bm4 = (const uint4*)(g_bmin + (size_t)row * NBLKS);

    if (t == 0) sh_ncand = 0;
    for (int i = t; i < NWARP * 256; i += 512) ((unsigned*)whist)[i] = 0;
    __syncthreads();

    // pass A1: histogram of bmin high byte (uint4: 8 blocks per thread-iter)
    for (int i = t; i < NV4; i += 512) {
        uint4 v = bm4[i];
        if (i == NV4 - 1) { v.z = 0xFFFFFFFFu; v.w = 0xFFFFFFFFu; }  // pad blocks
        unsigned w[4] = {v.x, v.y, v.z, v.w};
#pragma unroll
        for (int q = 0; q < 4; q++) {
            atomicAdd(&whist[warp][(w[q] & 0xFFFFu) >> 8], 1u);
            atomicAdd(&whist[warp][w[q] >> 24], 1u);
        }
    }
    __syncthreads();
    if (t < 256) {
        unsigned s = 0;
#pragma unroll
        for (int w = 0; w < NWARP; w++) s += whist[w][t];
        hist[t] = s;
    }
    __syncthreads();
    if (t == 0) {
        unsigned cum = 0;
        int b = 0;
        for (; b < 255; b++) {
            if (cum + hist[b] >= (unsigned)RANK) break;
            cum += hist[b];
        }
        sh_b1 = (unsigned)b;
        sh_base = cum;
    }
    __syncthreads();
    for (int i = t; i < NWARP * 256; i += 512) ((unsigned*)whist)[i] = 0;
    __syncthreads();

    // pass A2: low-byte histogram among bmins with high byte == b1
    const unsigned b1 = sh_b1;
    for (int i = t; i < NV4; i += 512) {
        uint4 v = bm4[i];
        if (i == NV4 - 1) { v.z = 0xFFFFFFFFu; v.w = 0xFFFFFFFFu; }
        unsigned w[4] = {v.x, v.y, v.z, v.w};
#pragma unroll
        for (int q = 0; q < 4; q++) {
            unsigned lo = w[q] & 0xFFFFu, hi = w[q] >> 16;
            if ((lo >> 8) == b1) atomicAdd(&whist[warp][lo & 255u], 1u);
            if ((hi >> 8) == b1) atomicAdd(&whist[warp][hi & 255u], 1u);
        }
    }
    __syncthreads();
    if (t < 256) {
        unsigned s = 0;
#pragma unroll
        for (int w = 0; w < NWARP; w++) s += whist[w][t];
        hist[t] = s;
    }
    __syncthreads();
    if (t == 0) {
        unsigned cum = sh_base;
        int b = 0;
        for (; b < 255; b++) {
            if (cum + hist[b] >= (unsigned)RANK) break;
            cum += hist[b];
        }
        unsigned T0 = (b1 << 8) | (unsigned)b;        // rank-RANK bmin
        unsigned Tm = f2ord16(ord162f(T0) + MARGIN) + 1;
        if (Tm > 65535u) Tm = 65535u;
        sh_T = (Tm > T0) ? Tm : T0;
    }
    __syncthreads();

    // pass B: expand hit blocks into candidate list
    const unsigned T = sh_T;
    int* cand = g_cand + (size_t)row * CCAP;
    const unsigned short* keys = g_keys16 + (size_t)row * C_;
    for (int i = t; i < NV4; i += 512) {
        uint4 v = bm4[i];
        if (i == NV4 - 1) { v.z = 0xFFFFFFFFu; v.w = 0xFFFFFFFFu; }
        unsigned w[4] = {v.x, v.y, v.z, v.w};
#pragma unroll
        for (int q = 0; q < 4; q++) {
#pragma unroll
            for (int h = 0; h < 2; h++) {
                unsigned bm = (h == 0) ? (w[q] & 0xFFFFu) : (w[q] >> 16);
                if (bm <= T) {
                    int blk = i * 8 + q * 2 + h;      // < NBLK by pad masking
                    uint4 kv = *(const uint4*)(keys + blk * 8);
                    unsigned kw[4] = {kv.x, kv.y, kv.z, kv.w};
                    int col = blk * 8;
#pragma unroll
                    for (int e = 0; e < 4; e++) {
                        if ((kw[e] & 0xFFFFu) <= T) {
                            int pos = atomicAdd(&sh_ncand, 1);
                            if (pos < CCAP) cand[pos] = col + e * 2;
                        }
                        if ((kw[e] >> 16) <= T) {
                            int pos = atomicAdd(&sh_ncand, 1);
                            if (pos < CCAP) cand[pos] = col + e * 2 + 1;
                        }
                    }
                }
            }
        }
    }
    __syncthreads();
    if (t == 0) g_ccnt[row] = min(sh_ncand, CCAP);
}

// ---------------- kernel 4: exact rescore + rank-select + histogram + log -----
// Warp handles TWO adjacent candidates per iteration (interleaved loads, 2x MLP).
__global__ __launch_bounds__(512) void rescore_kernel(const float* __restrict__ features,
                                                      const float* __restrict__ centres,
                                                      const int*   __restrict__ labels,
                                                      const float* __restrict__ weight,
                                                      float* __restrict__ out) {
    const int row = blockIdx.x;
    __shared__ unsigned long long cnd[CCAP];   // 16KB
    __shared__ float f[D_];
    __shared__ float p[NCLS];
    __shared__ float red[NWARP];
    const int t = threadIdx.x;
    const int warp = t >> 5, lane = t & 31;

    for (int i = t; i < D_; i += 512) f[i] = features[(size_t)row * D_ + i];
    for (int i = t; i < NCLS; i += 512) p[i] = 0.f;
    __syncthreads();

    const int cnt = g_ccnt[row];
    const int* cand = g_cand + (size_t)row * CCAP;

    // exact fp32 d2: warp per candidate PAIR (interleaved gathers, MLP 8/lane)
    for (int ci = warp * 2; ci < cnt; ci += NWARP * 2) {
        const bool two = (ci + 1 < cnt);
        int idx0 = cand[ci];
        int idx1 = two ? cand[ci + 1] : idx0;
        const float4* c0 = (const float4*)(centres + (size_t)idx0 * D_);
        const float4* c1 = (const float4*)(centres + (size_t)idx1 * D_);
        const float4* fs = (const float4*)f;
        float4 cv0[4], cv1[4];
#pragma unroll
        for (int k = 0; k < 4; k++) {
            int j = lane + 32 * k;
            cv0[k] = c0[j];
            cv1[k] = c1[j];
        }
        float s0 = 0.f, s1 = 0.f;
#pragma unroll
        for (int k = 0; k < 4; k++) {
            int j = lane + 32 * k;
            float4 fv = fs[j];
            float dx = fv.x - cv0[k].x, dy = fv.y - cv0[k].y;
            float dz = fv.z - cv0[k].z, dw = fv.w - cv0[k].w;
            s0 += dx * dx + dy * dy + dz * dz + dw * dw;
            dx = fv.x - cv1[k].x; dy = fv.y - cv1[k].y;
            dz = fv.z - cv1[k].z; dw = fv.w - cv1[k].w;
            s1 += dx * dx + dy * dy + dz * dz + dw * dw;
        }
#pragma unroll
        for (int o = 16; o; o >>= 1) {
            s0 += __shfl_xor_sync(0xffffffffu, s0, o);
            s1 += __shfl_xor_sync(0xffffffffu, s1, o);
        }
        if (lane == 0) {
            cnd[ci] = ((unsigned long long)f2ord(s0) << 32) | (unsigned)idx0;
            if (two)
                cnd[ci + 1] = ((unsigned long long)f2ord(s1) << 32) | (unsigned)idx1;
        }
    }
    __syncthreads();

    // rank-count selection (order-free; ranks unique since idx in low bits;
    // ties by ascending idx match JAX top_k order)
    for (int ci = t; ci < cnt; ci += 512) {
        unsigned long long v = cnd[ci];
        int r = 0;
        for (int q = 0; q < cnt; q++) r += (cnd[q] < v);
        if (r < KNN) {
            int idx = (int)(v & 0xffffffffull);
            float d2 = ord2f((unsigned)(v >> 32));
            float d = expf(-d2 * GCONST) * expf(weight[idx]);
            atomicAdd(&p[labels[idx]], d);
        }
    }
    __syncthreads();

    float partial = 0.f;
    for (int i = t; i < NCLS; i += 512) {
        float v = p[i];
        if (v == 0.f) v = 1e-10f;
        p[i] = v;
        partial += v;
    }
#pragma unroll
    for (int o = 16; o; o >>= 1) partial += __shfl_xor_sync(0xffffffffu, partial, o);
    if (lane == 0) red[warp] = partial;
    __syncthreads();
    if (t < 32) {
        float v = (t < NWARP) ? red[t] : 0.f;
#pragma unroll
        for (int o = 8; o; o >>= 1) v += __shfl_xor_sync(0xffffffffu, v, o);
        if (t == 0) red[0] = v;
    }
    __syncthreads();
    const float sum = red[0];
    for (int i = t; i < NCLS; i += 512)
        out[(size_t)row * NCLS + i] = logf(p[i] / sum);
}

// ---------------- launcher ----------------------------------------------------
extern "C" void kernel_launch(void* const* d_in, const int* in_sizes, int n_in,
                              void* d_out, int out_size) {
    const float* features = (const float*)d_in[0];   // [512, 512]
    const float* centres  = (const float*)d_in[1];   // [100000, 512]
    const int*   labels   = (const int*)d_in[2];     // [100000]
    const float* weight   = (const float*)d_in[3];   // [100000]
    float* out = (float*)d_out;                      // [512, 1000]

    cudaFuncSetAttribute(gemm_kernel,
                         cudaFuncAttributeMaxDynamicSharedMemorySize, GSMEM);

    convert_kernel<<<(C_ + B_ + 7) / 8, 256>>>(centres, features);

    dim3 gg(B_ / 128, (C_ + 127) / 128);   // x = m-tile (fast), y = c-tile
    gemm_kernel<<<gg, 256, GSMEM>>>();

    select_kernel<<<B_, 512>>>();

    rescore_kernel<<<B_, 512>>>(features, centres, labels, weight, out);
}